// round 7
// baseline (speedup 1.0000x reference)
#include <cuda_runtime.h>
#include <cuda_fp16.h>
#include <math.h>

#define NN 50000
#define NE 1600000
#define HID 32
#define IN_DIM 256
#define NCLS 40
#define NMID 30
#define FULL 0xffffffffu
#define NBLK_SCAN 196   // ceil(50000/256)

// ---------------- scratch (static device allocations) ----------------
__device__ __align__(256) float2 g_tmp2[NN * (HID / 2)];   // pre-agg features (fp32, dinv-scaled)
__device__ __align__(256) float g_h1[NN * HID];            // post LN features (fp32)
__device__ __align__(256) __half2 g_h1h[NN * (HID / 2)];   // post LN features (fp16)
__device__ __align__(256) float g_x0[NN * HID];            // residual projection
__device__ __align__(256) float g_tmp40[NN * NCLS];        // final-layer pre-agg (fp32)
__device__ float g_dinv[NN];
__device__ float g_cntinv[NN];
__device__ int g_cnt_col[NN];
__device__ int g_cnt_row[NN];
__device__ int g_colptr[NN + 1];
__device__ int g_rowptr[NN + 1];
__device__ int g_fill_c[NN];
__device__ int g_fill_r[NN];
__device__ int g_gsrc[NE];     // CSR by col: source node per edge
__device__ int g_midx[NE];     // CSR by row: col node per edge
__device__ float g_u[NN];      // scalar sum_j w2_j |h - hm|
__device__ float g_t[NN];      // scalar sum_j (w1_j hm_j h_j + w3_j h_j)
__device__ int g_bsum[2 * NBLK_SCAN];
__device__ int g_bscan[2 * NBLK_SCAN];

__device__ __forceinline__ float wsum(float v) {
#pragma unroll
    for (int o = 16; o > 0; o >>= 1) v += __shfl_xor_sync(FULL, v, o);
    return v;
}

// ---------------- CSR build ----------------
__global__ void k_zero() {
    int i = blockIdx.x * blockDim.x + threadIdx.x;
    if (i < NN) { g_cnt_col[i] = 0; g_cnt_row[i] = 0; }
}

__global__ void k_count(const int* __restrict__ row, const int* __restrict__ col) {
    int e = blockIdx.x * blockDim.x + threadIdx.x;
    if (e < NE) {
        atomicAdd(&g_cnt_col[col[e]], 1);
        atomicAdd(&g_cnt_row[row[e]], 1);
    }
}

__global__ void k_node_prep() {
    int i = blockIdx.x * blockDim.x + threadIdx.x;
    if (i < NN) {
        float deg = (float)(g_cnt_col[i] + 1);   // +1 self loop
        g_dinv[i] = rsqrtf(deg);
        int c = g_cnt_row[i];
        if (c < 1) c = 1;
        g_cntinv[i] = 1.0f / (float)c;
    }
}

// pass 1: per-block exclusive scan of both count arrays; block totals to g_bsum
__global__ void k_scan1() {
    const int* cnt = blockIdx.y ? g_cnt_row : g_cnt_col;
    int* ptr = blockIdx.y ? g_rowptr : g_colptr;
    __shared__ int wt[8];
    int t = threadIdx.x, lane = t & 31, wid = t >> 5;
    int i = blockIdx.x * 256 + t;
    int v = (i < NN) ? cnt[i] : 0;
    int x = v;
#pragma unroll
    for (int o = 1; o < 32; o <<= 1) {
        int y = __shfl_up_sync(FULL, x, o);
        if (lane >= o) x += y;
    }
    if (lane == 31) wt[wid] = x;
    __syncthreads();
    if (wid == 0 && lane < 8) {
        int wv = wt[lane];
        int xs = wv;
#pragma unroll
        for (int o = 1; o < 8; o <<= 1) {
            int y = __shfl_up_sync(0xff, xs, o);
            if (lane >= o) xs += y;
        }
        wt[lane] = xs - wv;
    }
    __syncthreads();
    int excl = x - v + wt[wid];
    if (i < NN) ptr[i] = excl;
    if (t == 255) g_bsum[blockIdx.y * NBLK_SCAN + blockIdx.x] = excl + v;
}

// pass 2: scan block totals (2 arrays, one warp each)
__global__ void k_scan2() {
    int w = threadIdx.x >> 5;
    int lane = threadIdx.x & 31;
    if (w >= 2) return;
    int carry = 0;
    for (int base = 0; base < NBLK_SCAN; base += 32) {
        int idx = base + lane;
        int v = (idx < NBLK_SCAN) ? g_bsum[w * NBLK_SCAN + idx] : 0;
        int x = v;
#pragma unroll
        for (int o = 1; o < 32; o <<= 1) {
            int y = __shfl_up_sync(FULL, x, o);
            if (lane >= o) x += y;
        }
        if (idx < NBLK_SCAN) g_bscan[w * NBLK_SCAN + idx] = x - v + carry;
        carry += __shfl_sync(FULL, x, 31);
    }
}

// pass 3: add block offsets; init fill cursors; set sentinels
__global__ void k_scan3() {
    int* ptr = blockIdx.y ? g_rowptr : g_colptr;
    int* fill = blockIdx.y ? g_fill_r : g_fill_c;
    int i = blockIdx.x * 256 + threadIdx.x;
    if (i < NN) {
        int p = ptr[i] + g_bscan[blockIdx.y * NBLK_SCAN + blockIdx.x];
        ptr[i] = p;
        fill[i] = p;
    }
    if (i == 0) ptr[NN] = NE;
}

__global__ void k_fill(const int* __restrict__ row, const int* __restrict__ col) {
    int e = blockIdx.x * blockDim.x + threadIdx.x;
    if (e < NE) {
        int r = row[e], c = col[e];
        int p = atomicAdd(&g_fill_c[c], 1);
        g_gsrc[p] = r;
        int q = atomicAdd(&g_fill_r[r], 1);
        g_midx[q] = c;
    }
}

// ---------------- GEMMs ----------------
// warp-per-node, 8 nodes per warp, W resident in smem (one load per block).
// MODE 0: g_tmp2 = (X @ W) * dinv[row]   (first GCN layer, fp32)
// MODE 1: g_x0   = LN(relu(X @ W))       (residual projection, fp32)
template <int MODE>
__global__ __launch_bounds__(256) void k_gemm256(const float* __restrict__ X,
                                                 const float* __restrict__ W,
                                                 const float* __restrict__ gam,
                                                 const float* __restrict__ bet) {
    __shared__ float Ws[IN_DIM * HID];  // 32 KB
    int tid = threadIdx.x;
    for (int q = tid; q < IN_DIM * HID; q += 256) Ws[q] = W[q];
    __syncthreads();
    int lane = tid & 31;
    int wrp = (blockIdx.x * 256 + tid) >> 5;   // global warp id
    int node0 = wrp * 8;
#pragma unroll 1
    for (int n = 0; n < 8; n++) {
        int node = node0 + n;
        if (node >= NN) return;
        const float* xr = X + node * IN_DIM;
        float acc = 0.0f;
#pragma unroll
        for (int q = 0; q < 8; q++) {
            float xv = xr[q * 32 + lane];
#pragma unroll
            for (int l = 0; l < 32; l++) {
                float xk = __shfl_sync(FULL, xv, l);
                acc = fmaf(xk, Ws[((q << 5) + l) * HID + lane], acc);
            }
        }
        if (MODE == 0) {
            ((float*)g_tmp2)[node * HID + lane] = acc * g_dinv[node];
        } else {
            float r = fmaxf(acc, 0.0f);
            float mu = wsum(r) * (1.0f / HID);
            float d = r - mu;
            float var = wsum(d * d) * (1.0f / HID);
            g_x0[node * HID + lane] = d * rsqrtf(var + 1e-5f) * gam[lane] + bet[lane];
        }
    }
}

// ---------------- Fused edge kernels (warp per node, paired-edge) ----------------
// GCN aggregation (CSR by col, fp32 float2 rows, 2 edges/iter) + bias + relu + LN
__global__ __launch_bounds__(256) void k_gcn_ln(const float* __restrict__ bias,
                                                const float* __restrict__ gam,
                                                const float* __restrict__ bet) {
    int i = (blockIdx.x * blockDim.x + threadIdx.x) >> 5;
    if (i >= NN) return;
    int lane = threadIdx.x & 31;
    int lh = lane & 15;          // feature-pair index
    int hi16 = lane & 16;        // 0 for low half, 16 for high half
    int s = g_colptr[i], e = g_colptr[i + 1];
    float2 acc;
    {   // self loop (row already scaled by dinv[i]); count once (low half only)
        float2 a = g_tmp2[i * 16 + lh];
        if (hi16) { a.x = 0.0f; a.y = 0.0f; }
        acc = a;
    }
    for (int base = s; base < e; base += 32) {
        int idx = base + lane;
        int src = 0;
        if (idx < e) src = g_gsrc[idx];
        int m = min(32, e - base);
        if (m == 32) {
#pragma unroll
            for (int k = 0; k < 16; k++) {
                int s0 = __shfl_sync(FULL, src, k + hi16);
                float2 a = g_tmp2[s0 * 16 + lh];
                acc.x += a.x; acc.y += a.y;
            }
        } else {
            int kmax = min(16, m);
            for (int k = 0; k < kmax; k++) {
                int ei = k + hi16;
                int s0 = __shfl_sync(FULL, src, ei);
                if (ei < m) {
                    float2 a = g_tmp2[s0 * 16 + lh];
                    acc.x += a.x; acc.y += a.y;
                }
            }
        }
    }
    acc.x += __shfl_xor_sync(FULL, acc.x, 16);
    acc.y += __shfl_xor_sync(FULL, acc.y, 16);
    float di = g_dinv[i];
    float2 b2 = ((const float2*)bias)[lh];
    float rx = fmaxf(fmaf(acc.x, di, b2.x), 0.0f);
    float ry = fmaxf(fmaf(acc.y, di, b2.y), 0.0f);
    float mu = wsum(rx + ry) * (1.0f / 64.0f);   // each feature counted twice
    float dx = rx - mu, dy = ry - mu;
    float var = wsum(dx * dx + dy * dy) * (1.0f / 64.0f);
    float rstd = rsqrtf(var + 1e-5f);
    float2 g2 = ((const float2*)gam)[lh];
    float2 be2 = ((const float2*)bet)[lh];
    float ox = dx * rstd * g2.x + be2.x;
    float oy = dy * rstd * g2.y + be2.y;
    if (lane < 16) {
        float2 o2; o2.x = ox; o2.y = oy;
        ((float2*)g_h1)[i * 16 + lh] = o2;
        g_h1h[i * 16 + lh] = __float22half2_rn(o2);
    }
}

// mean_agg over fp16 h1 (CSR by row, 2 edges/iter) + scalar score terms
__global__ __launch_bounds__(256) void k_mean(const float* __restrict__ ws) {
    int i = (blockIdx.x * blockDim.x + threadIdx.x) >> 5;
    if (i >= NN) return;
    int lane = threadIdx.x & 31;
    int lh = lane & 15;
    int hi16 = lane & 16;
    int s = g_rowptr[i], e = g_rowptr[i + 1];
    float2 acc; acc.x = 0.0f; acc.y = 0.0f;
    for (int base = s; base < e; base += 32) {
        int idx = base + lane;
        int src = 0;
        if (idx < e) src = g_midx[idx];
        int m = min(32, e - base);
        if (m == 32) {
#pragma unroll
            for (int k = 0; k < 16; k++) {
                int s0 = __shfl_sync(FULL, src, k + hi16);
                float2 a = __half22float2(g_h1h[s0 * 16 + lh]);
                acc.x += a.x; acc.y += a.y;
            }
        } else {
            int kmax = min(16, m);
            for (int k = 0; k < kmax; k++) {
                int ei = k + hi16;
                int s0 = __shfl_sync(FULL, src, ei);
                if (ei < m) {
                    float2 a = __half22float2(g_h1h[s0 * 16 + lh]);
                    acc.x += a.x; acc.y += a.y;
                }
            }
        }
    }
    acc.x += __shfl_xor_sync(FULL, acc.x, 16);
    acc.y += __shfl_xor_sync(FULL, acc.y, 16);
    float ci = g_cntinv[i];
    float hmx = acc.x * ci, hmy = acc.y * ci;
    float2 hv = ((const float2*)g_h1)[i * 16 + lh];
    float2 w1 = ((const float2*)ws)[lh];
    float2 w2 = ((const float2*)ws)[16 + lh];
    float2 w3 = ((const float2*)ws)[32 + lh];
    float up = w2.x * fabsf(hv.x - hmx) + w2.y * fabsf(hv.y - hmy);
    float tp = w1.x * hmx * hv.x + w3.x * hv.x + w1.y * hmy * hv.y + w3.y * hv.y;
    float us = wsum(up) * 0.5f;   // features counted twice
    float ts = wsum(tp) * 0.5f;
    if (lane == 0) { g_u[i] = us; g_t[i] = ts; }
}

// scalar mean_agg(u) + sigmoid gate + residual combine + next-layer GEMM (shuffle
// broadcast), dinv folded. NC=32 -> g_tmp2 (fp32), NC=40 -> g_tmp40 (fp32).
template <int NC>
__global__ __launch_bounds__(256) void k_combine_gemm(const float* __restrict__ W) {
    __shared__ float Ws[HID * NC];
    int tid = threadIdx.x;
    for (int q = tid; q < HID * NC; q += 256) Ws[q] = W[q];
    __syncthreads();
    int i = (blockIdx.x * blockDim.x + tid) >> 5;
    if (i >= NN) return;
    int lane = tid & 31;
    int s = g_rowptr[i], e = g_rowptr[i + 1];
    float a = 0.0f;
    for (int j = s + lane; j < e; j += 32) a += g_u[g_midx[j]];
    a = wsum(a);
    float z = g_t[i] + a * g_cntinv[i];
    float sc = 1.0f / (1.0f + expf(-z));
    float hn = (1.0f - sc) * g_h1[i * HID + lane] + sc * g_x0[i * HID + lane];
    float di = g_dinv[i];
    float acc0 = 0.0f, acc1 = 0.0f;
#pragma unroll
    for (int k = 0; k < HID; k++) {
        float hk = __shfl_sync(FULL, hn, k);
        acc0 = fmaf(hk, Ws[k * NC + lane], acc0);
        if (NC > 32) {
            int c = 32 + lane;
            acc1 = fmaf(hk, (c < NC) ? Ws[k * NC + c] : 0.0f, acc1);
        }
    }
    if (NC == 32) {
        ((float*)g_tmp2)[i * HID + lane] = acc0 * di;
    } else {
        g_tmp40[i * NC + lane] = acc0 * di;
        if (lane < NC - 32) g_tmp40[i * NC + 32 + lane] = acc1 * di;
    }
}

// final GCN aggregation over 40 classes + bias, direct to output (fp32)
__global__ __launch_bounds__(256) void k_agg40(const float* __restrict__ bias,
                                               float* __restrict__ out) {
    int i = (blockIdx.x * blockDim.x + threadIdx.x) >> 5;
    if (i >= NN) return;
    int lane = threadIdx.x & 31;
    int s = g_colptr[i], e = g_colptr[i + 1];
    bool two = lane < (NCLS - 32);
    float acc0 = g_tmp40[i * NCLS + lane];  // self loop (row scaled by dinv[i])
    float acc1 = two ? g_tmp40[i * NCLS + 32 + lane] : 0.0f;
    for (int base = s; base < e; base += 32) {
        int idx = base + lane;
        int src = 0;
        if (idx < e) src = g_gsrc[idx];
        int m = min(32, e - base);
        for (int k = 0; k < m; k++) {
            int s0 = __shfl_sync(FULL, src, k);
            acc0 += g_tmp40[s0 * NCLS + lane];
            if (two) acc1 += g_tmp40[s0 * NCLS + 32 + lane];
        }
    }
    float di = g_dinv[i];
    out[i * NCLS + lane] = fmaf(acc0, di, bias[lane]);
    if (two) out[i * NCLS + 32 + lane] = fmaf(acc1, di, bias[32 + lane]);
}

// ---------------- host launcher ----------------
extern "C" void kernel_launch(void* const* d_in, const int* in_sizes, int n_in,
                              void* d_out, int out_size) {
    const float* x = (const float*)d_in[0];
    const int* ei = (const int*)d_in[1];
    const int* row = ei;
    const int* col = ei + NE;
    const float* W0 = (const float*)d_in[2];
    const float* b0 = (const float*)d_in[3];
    const float* Whh = (const float*)d_in[4];
    const float* bhh = (const float*)d_in[5];
    const float* Wl = (const float*)d_in[6];
    const float* bl = (const float*)d_in[7];
    const float* lng0 = (const float*)d_in[8];
    const float* lnb0 = (const float*)d_in[9];
    const float* lngm = (const float*)d_in[10];
    const float* lnbm = (const float*)d_in[11];
    const float* wws = (const float*)d_in[12];
    const float* Wres = (const float*)d_in[13];
    const float* rg = (const float*)d_in[14];
    const float* rb = (const float*)d_in[15];
    float* out = (float*)d_out;

    const int nb_node = (NN + 255) / 256;        // 196
    const int nb_warp = (NN * 32 + 255) / 256;   // 6250 (warp per node)
    const int nb_edge = (NE + 255) / 256;        // 6250
    const int nb_g256 = (NN + 63) / 64;          // 782 (64 nodes per block)
    dim3 scan_grid(NBLK_SCAN, 2);

    // CSR build
    k_zero<<<nb_node, 256>>>();
    k_count<<<nb_edge, 256>>>(row, col);
    k_node_prep<<<nb_node, 256>>>();
    k_scan1<<<scan_grid, 256>>>();
    k_scan2<<<1, 64>>>();
    k_scan3<<<scan_grid, 256>>>();
    k_fill<<<nb_edge, 256>>>(row, col);

    // residual projection x0 = LN(relu(x @ W_res))
    k_gemm256<1><<<nb_g256, 256>>>(x, Wres, rg, rb);

    // first block (input dim 256); gemm pre-scaled by dinv
    k_gemm256<0><<<nb_g256, 256>>>(x, W0, (const float*)0, (const float*)0);
    k_gcn_ln<<<nb_warp, 256>>>(b0, lng0, lnb0);
    k_mean<<<nb_warp, 256>>>(wws);
    k_combine_gemm<HID><<<nb_warp, 256>>>(Whh);  // prepares tmp for block 1

    // middle blocks 1..30 (weights Whh[0..29]); combine applies NEXT weight
    for (int m = 0; m < NMID; m++) {
        k_gcn_ln<<<nb_warp, 256>>>(bhh + m * HID, lngm + m * HID, lnbm + m * HID);
        k_mean<<<nb_warp, 256>>>(wws);
        if (m < NMID - 1)
            k_combine_gemm<HID><<<nb_warp, 256>>>(Whh + (m + 1) * HID * HID);
        else
            k_combine_gemm<NCLS><<<nb_warp, 256>>>(Wl);
    }

    // final GCN aggregation (32 -> 40 classes)
    k_agg40<<<nb_warp, 256>>>(bl, out);
}

// round 8
// speedup vs baseline: 1.0875x; 1.0875x over previous
#include <cuda_runtime.h>
#include <cuda_fp16.h>
#include <math.h>

#define NN 50000
#define NE 1600000
#define HID 32
#define IN_DIM 256
#define NCLS 40
#define NMID 30
#define FULL 0xffffffffu
#define NBLK_SCAN 196   // ceil(50000/256)

// ---------------- scratch (static device allocations) ----------------
__device__ __align__(256) float g_tmp[NN * HID];     // pre-agg features (fp32, dinv-scaled)
__device__ __align__(256) float g_h1[NN * HID];      // post LN features (fp32)
__device__ __align__(256) __half g_h1h[NN * HID];    // post LN features (fp16, mean gather)
__device__ __align__(256) float g_x0[NN * HID];      // residual projection
__device__ __align__(256) float g_tmp40[NN * NCLS];  // final-layer pre-agg (fp32)
__device__ float g_dinv[NN];
__device__ float g_cntinv[NN];
__device__ int g_cnt_col[NN];
__device__ int g_cnt_row[NN];
__device__ int g_colptr[NN + 1];
__device__ int g_rowptr[NN + 1];
__device__ int g_fill_c[NN];
__device__ int g_fill_r[NN];
__device__ int g_gsrc[NE];     // CSR by col: source node per edge
__device__ int g_midx[NE];     // CSR by row: col node per edge
__device__ float g_u[NN];      // scalar sum_j w2_j |h - hm|
__device__ float g_t[NN];      // scalar sum_j (w1_j hm_j h_j + w3_j h_j)
__device__ int g_bsum[2 * NBLK_SCAN];
__device__ int g_bscan[2 * NBLK_SCAN];

__device__ __forceinline__ float wsum(float v) {
#pragma unroll
    for (int o = 16; o > 0; o >>= 1) v += __shfl_xor_sync(FULL, v, o);
    return v;
}

// ---------------- CSR build ----------------
__global__ void k_zero() {
    int i = blockIdx.x * blockDim.x + threadIdx.x;
    if (i < NN) { g_cnt_col[i] = 0; g_cnt_row[i] = 0; }
}

__global__ void k_count(const int* __restrict__ row, const int* __restrict__ col) {
    int e = blockIdx.x * blockDim.x + threadIdx.x;
    if (e < NE) {
        atomicAdd(&g_cnt_col[col[e]], 1);
        atomicAdd(&g_cnt_row[row[e]], 1);
    }
}

// pass 1: per-block exclusive scan of both count arrays; block totals to g_bsum.
// Also computes per-node dinv (from col counts) / cntinv (from row counts).
__global__ void k_scan1() {
    const int* cnt = blockIdx.y ? g_cnt_row : g_cnt_col;
    int* ptr = blockIdx.y ? g_rowptr : g_colptr;
    __shared__ int wt[8];
    int t = threadIdx.x, lane = t & 31, wid = t >> 5;
    int i = blockIdx.x * 256 + t;
    int v = (i < NN) ? cnt[i] : 0;
    if (i < NN) {
        if (blockIdx.y == 0) {
            g_dinv[i] = rsqrtf((float)(v + 1));   // +1 self loop
        } else {
            int c = v < 1 ? 1 : v;
            g_cntinv[i] = 1.0f / (float)c;
        }
    }
    int x = v;
#pragma unroll
    for (int o = 1; o < 32; o <<= 1) {
        int y = __shfl_up_sync(FULL, x, o);
        if (lane >= o) x += y;
    }
    if (lane == 31) wt[wid] = x;
    __syncthreads();
    if (wid == 0 && lane < 8) {
        int wv = wt[lane];
        int xs = wv;
#pragma unroll
        for (int o = 1; o < 8; o <<= 1) {
            int y = __shfl_up_sync(0xff, xs, o);
            if (lane >= o) xs += y;
        }
        wt[lane] = xs - wv;
    }
    __syncthreads();
    int excl = x - v + wt[wid];
    if (i < NN) ptr[i] = excl;
    if (t == 255) g_bsum[blockIdx.y * NBLK_SCAN + blockIdx.x] = excl + v;
}

// pass 2: scan block totals (2 arrays, one warp each)
__global__ void k_scan2() {
    int w = threadIdx.x >> 5;
    int lane = threadIdx.x & 31;
    if (w >= 2) return;
    int carry = 0;
    for (int base = 0; base < NBLK_SCAN; base += 32) {
        int idx = base + lane;
        int v = (idx < NBLK_SCAN) ? g_bsum[w * NBLK_SCAN + idx] : 0;
        int x = v;
#pragma unroll
        for (int o = 1; o < 32; o <<= 1) {
            int y = __shfl_up_sync(FULL, x, o);
            if (lane >= o) x += y;
        }
        if (idx < NBLK_SCAN) g_bscan[w * NBLK_SCAN + idx] = x - v + carry;
        carry += __shfl_sync(FULL, x, 31);
    }
}

// pass 3: add block offsets; init fill cursors; set sentinels
__global__ void k_scan3() {
    int* ptr = blockIdx.y ? g_rowptr : g_colptr;
    int* fill = blockIdx.y ? g_fill_r : g_fill_c;
    int i = blockIdx.x * 256 + threadIdx.x;
    if (i < NN) {
        int p = ptr[i] + g_bscan[blockIdx.y * NBLK_SCAN + blockIdx.x];
        ptr[i] = p;
        fill[i] = p;
    }
    if (i == 0) ptr[NN] = NE;
}

__global__ void k_fill(const int* __restrict__ row, const int* __restrict__ col) {
    int e = blockIdx.x * blockDim.x + threadIdx.x;
    if (e < NE) {
        int r = row[e], c = col[e];
        int p = atomicAdd(&g_fill_c[c], 1);
        g_gsrc[p] = r;
        int q = atomicAdd(&g_fill_r[r], 1);
        g_midx[q] = c;
    }
}

// ---------------- GEMMs ----------------
// warp-per-node, 8 nodes per warp, W resident in smem (one load per block).
// MODE 0: g_tmp = (X @ W) * dinv[row]   (first GCN layer, fp32)
// MODE 1: g_x0  = LN(relu(X @ W))       (residual projection, fp32)
template <int MODE>
__global__ __launch_bounds__(256) void k_gemm256(const float* __restrict__ X,
                                                 const float* __restrict__ W,
                                                 const float* __restrict__ gam,
                                                 const float* __restrict__ bet) {
    __shared__ float Ws[IN_DIM * HID];  // 32 KB
    int tid = threadIdx.x;
    for (int q = tid; q < IN_DIM * HID; q += 256) Ws[q] = W[q];
    __syncthreads();
    int lane = tid & 31;
    int wrp = (blockIdx.x * 256 + tid) >> 5;   // global warp id
    int node0 = wrp * 8;
#pragma unroll 1
    for (int n = 0; n < 8; n++) {
        int node = node0 + n;
        if (node >= NN) return;
        const float* xr = X + node * IN_DIM;
        float acc = 0.0f;
#pragma unroll
        for (int q = 0; q < 8; q++) {
            float xv = xr[q * 32 + lane];
#pragma unroll
            for (int l = 0; l < 32; l++) {
                float xk = __shfl_sync(FULL, xv, l);
                acc = fmaf(xk, Ws[((q << 5) + l) * HID + lane], acc);
            }
        }
        if (MODE == 0) {
            g_tmp[node * HID + lane] = acc * g_dinv[node];
        } else {
            float r = fmaxf(acc, 0.0f);
            float mu = wsum(r) * (1.0f / HID);
            float d = r - mu;
            float var = wsum(d * d) * (1.0f / HID);
            g_x0[node * HID + lane] = d * rsqrtf(var + 1e-5f) * gam[lane] + bet[lane];
        }
    }
}

// ---------------- Fused edge kernels (warp per node, 8-wide load batches) ----------------
// GCN aggregation (CSR by col, unweighted over dinv-scaled rows) + bias + relu + LN
__global__ __launch_bounds__(512) void k_gcn_ln(const float* __restrict__ bias,
                                                const float* __restrict__ gam,
                                                const float* __restrict__ bet) {
    int i = (blockIdx.x * blockDim.x + threadIdx.x) >> 5;
    if (i >= NN) return;
    int lane = threadIdx.x & 31;
    int s = g_colptr[i], e = g_colptr[i + 1];
    float acc = g_tmp[i * HID + lane];  // self loop (row already scaled by dinv[i])
    int base = s;
    // full-chunk fast path: branch-free 8-wide batches (8 shfl -> 8 LDG -> tree add)
    for (; base + 32 <= e; base += 32) {
        int src = g_gsrc[base + lane];
#pragma unroll
        for (int k = 0; k < 32; k += 8) {
            int s0 = __shfl_sync(FULL, src, k);
            int s1 = __shfl_sync(FULL, src, k + 1);
            int s2 = __shfl_sync(FULL, src, k + 2);
            int s3 = __shfl_sync(FULL, src, k + 3);
            int s4 = __shfl_sync(FULL, src, k + 4);
            int s5 = __shfl_sync(FULL, src, k + 5);
            int s6 = __shfl_sync(FULL, src, k + 6);
            int s7 = __shfl_sync(FULL, src, k + 7);
            float a0 = g_tmp[s0 * HID + lane];
            float a1 = g_tmp[s1 * HID + lane];
            float a2 = g_tmp[s2 * HID + lane];
            float a3 = g_tmp[s3 * HID + lane];
            float a4 = g_tmp[s4 * HID + lane];
            float a5 = g_tmp[s5 * HID + lane];
            float a6 = g_tmp[s6 * HID + lane];
            float a7 = g_tmp[s7 * HID + lane];
            acc += ((a0 + a1) + (a2 + a3)) + ((a4 + a5) + (a6 + a7));
        }
    }
    if (base < e) {  // tail chunk (< 32 edges)
        int idx = base + lane;
        int src = (idx < e) ? g_gsrc[idx] : 0;
        int m = e - base;
        for (int k = 0; k < m; k++) {
            int s0 = __shfl_sync(FULL, src, k);
            acc += g_tmp[s0 * HID + lane];
        }
    }
    float v = fmaf(acc, g_dinv[i], bias[lane]);
    float r = fmaxf(v, 0.0f);
    float mu = wsum(r) * (1.0f / HID);
    float d = r - mu;
    float var = wsum(d * d) * (1.0f / HID);
    float o = d * rsqrtf(var + 1e-5f) * gam[lane] + bet[lane];
    g_h1[i * HID + lane] = o;
    g_h1h[i * HID + lane] = __float2half_rn(o);
}

// mean_agg over fp16 h1 (CSR by row, 8-wide load batches) + scalar score terms
__global__ __launch_bounds__(512) void k_mean(const float* __restrict__ ws) {
    int i = (blockIdx.x * blockDim.x + threadIdx.x) >> 5;
    if (i >= NN) return;
    int lane = threadIdx.x & 31;
    int s = g_rowptr[i], e = g_rowptr[i + 1];
    float acc = 0.0f;
    int base = s;
    for (; base + 32 <= e; base += 32) {
        int src = g_midx[base + lane];
#pragma unroll
        for (int k = 0; k < 32; k += 8) {
            int s0 = __shfl_sync(FULL, src, k);
            int s1 = __shfl_sync(FULL, src, k + 1);
            int s2 = __shfl_sync(FULL, src, k + 2);
            int s3 = __shfl_sync(FULL, src, k + 3);
            int s4 = __shfl_sync(FULL, src, k + 4);
            int s5 = __shfl_sync(FULL, src, k + 5);
            int s6 = __shfl_sync(FULL, src, k + 6);
            int s7 = __shfl_sync(FULL, src, k + 7);
            float a0 = __half2float(g_h1h[s0 * HID + lane]);
            float a1 = __half2float(g_h1h[s1 * HID + lane]);
            float a2 = __half2float(g_h1h[s2 * HID + lane]);
            float a3 = __half2float(g_h1h[s3 * HID + lane]);
            float a4 = __half2float(g_h1h[s4 * HID + lane]);
            float a5 = __half2float(g_h1h[s5 * HID + lane]);
            float a6 = __half2float(g_h1h[s6 * HID + lane]);
            float a7 = __half2float(g_h1h[s7 * HID + lane]);
            acc += ((a0 + a1) + (a2 + a3)) + ((a4 + a5) + (a6 + a7));
        }
    }
    if (base < e) {
        int idx = base + lane;
        int src = (idx < e) ? g_midx[idx] : 0;
        int m = e - base;
        for (int k = 0; k < m; k++) {
            int s0 = __shfl_sync(FULL, src, k);
            acc += __half2float(g_h1h[s0 * HID + lane]);
        }
    }
    float hm = acc * g_cntinv[i];
    float hv = g_h1[i * HID + lane];
    float up = ws[HID + lane] * fabsf(hv - hm);
    float tp = ws[lane] * hm * hv + ws[2 * HID + lane] * hv;
    float us = wsum(up);
    float ts = wsum(tp);
    if (lane == 0) { g_u[i] = us; g_t[i] = ts; }
}

// scalar mean_agg(u) + sigmoid gate + residual combine + next-layer GEMM (shuffle
// broadcast), dinv folded. NC=32 -> g_tmp, NC=40 -> g_tmp40.
template <int NC>
__global__ __launch_bounds__(512) void k_combine_gemm(const float* __restrict__ W) {
    __shared__ float Ws[HID * NC];
    int tid = threadIdx.x;
    for (int q = tid; q < HID * NC; q += 512) Ws[q] = W[q];
    __syncthreads();
    int i = (blockIdx.x * blockDim.x + tid) >> 5;
    if (i >= NN) return;
    int lane = tid & 31;
    int s = g_rowptr[i], e = g_rowptr[i + 1];
    float a = 0.0f;
    for (int j = s + lane; j < e; j += 32) a += g_u[g_midx[j]];
    a = wsum(a);
    float z = g_t[i] + a * g_cntinv[i];
    float sc = 1.0f / (1.0f + expf(-z));
    float hn = (1.0f - sc) * g_h1[i * HID + lane] + sc * g_x0[i * HID + lane];
    float di = g_dinv[i];
    float acc0 = 0.0f, acc1 = 0.0f;
#pragma unroll
    for (int k = 0; k < HID; k++) {
        float hk = __shfl_sync(FULL, hn, k);
        acc0 = fmaf(hk, Ws[k * NC + lane], acc0);
        if (NC > 32) {
            int c = 32 + lane;
            acc1 = fmaf(hk, (c < NC) ? Ws[k * NC + c] : 0.0f, acc1);
        }
    }
    if (NC == 32) {
        g_tmp[i * HID + lane] = acc0 * di;
    } else {
        g_tmp40[i * NC + lane] = acc0 * di;
        if (lane < NC - 32) g_tmp40[i * NC + 32 + lane] = acc1 * di;
    }
}

// final GCN aggregation over 40 classes + bias, direct to output (fp32)
__global__ __launch_bounds__(512) void k_agg40(const float* __restrict__ bias,
                                               float* __restrict__ out) {
    int i = (blockIdx.x * blockDim.x + threadIdx.x) >> 5;
    if (i >= NN) return;
    int lane = threadIdx.x & 31;
    int s = g_colptr[i], e = g_colptr[i + 1];
    bool two = lane < (NCLS - 32);
    float acc0 = g_tmp40[i * NCLS + lane];  // self loop (row scaled by dinv[i])
    float acc1 = two ? g_tmp40[i * NCLS + 32 + lane] : 0.0f;
    for (int base = s; base < e; base += 32) {
        int idx = base + lane;
        int src = 0;
        if (idx < e) src = g_gsrc[idx];
        int m = min(32, e - base);
        for (int k = 0; k < m; k++) {
            int s0 = __shfl_sync(FULL, src, k);
            acc0 += g_tmp40[s0 * NCLS + lane];
            if (two) acc1 += g_tmp40[s0 * NCLS + 32 + lane];
        }
    }
    float di = g_dinv[i];
    out[i * NCLS + lane] = fmaf(acc0, di, bias[lane]);
    if (two) out[i * NCLS + 32 + lane] = fmaf(acc1, di, bias[32 + lane]);
}

// ---------------- host launcher ----------------
extern "C" void kernel_launch(void* const* d_in, const int* in_sizes, int n_in,
                              void* d_out, int out_size) {
    const float* x = (const float*)d_in[0];
    const int* ei = (const int*)d_in[1];
    const int* row = ei;
    const int* col = ei + NE;
    const float* W0 = (const float*)d_in[2];
    const float* b0 = (const float*)d_in[3];
    const float* Whh = (const float*)d_in[4];
    const float* bhh = (const float*)d_in[5];
    const float* Wl = (const float*)d_in[6];
    const float* bl = (const float*)d_in[7];
    const float* lng0 = (const float*)d_in[8];
    const float* lnb0 = (const float*)d_in[9];
    const float* lngm = (const float*)d_in[10];
    const float* lnbm = (const float*)d_in[11];
    const float* wws = (const float*)d_in[12];
    const float* Wres = (const float*)d_in[13];
    const float* rg = (const float*)d_in[14];
    const float* rb = (const float*)d_in[15];
    float* out = (float*)d_out;

    const int nb_node = (NN + 255) / 256;          // 196
    const int nb_warp = (NN * 32 + 511) / 512;     // 3125 (warp per node, 512 thr)
    const int nb_edge = (NE + 255) / 256;          // 6250
    const int nb_g256 = (NN + 63) / 64;            // 782 (64 nodes per block)
    dim3 scan_grid(NBLK_SCAN, 2);

    // CSR build (node_prep folded into scan1)
    k_zero<<<nb_node, 256>>>();
    k_count<<<nb_edge, 256>>>(row, col);
    k_scan1<<<scan_grid, 256>>>();
    k_scan2<<<1, 64>>>();
    k_scan3<<<scan_grid, 256>>>();
    k_fill<<<nb_edge, 256>>>(row, col);

    // residual projection x0 = LN(relu(x @ W_res))
    k_gemm256<1><<<nb_g256, 256>>>(x, Wres, rg, rb);

    // first block (input dim 256); gemm pre-scaled by dinv
    k_gemm256<0><<<nb_g256, 256>>>(x, W0, (const float*)0, (const float*)0);
    k_gcn_ln<<<nb_warp, 512>>>(b0, lng0, lnb0);
    k_mean<<<nb_warp, 512>>>(wws);
    k_combine_gemm<HID><<<nb_warp, 512>>>(Whh);  // prepares tmp for block 1

    // middle blocks 1..30 (weights Whh[0..29]); combine applies NEXT weight
    for (int m = 0; m < NMID; m++) {
        k_gcn_ln<<<nb_warp, 512>>>(bhh + m * HID, lngm + m * HID, lnbm + m * HID);
        k_mean<<<nb_warp, 512>>>(wws);
        if (m < NMID - 1)
            k_combine_gemm<HID><<<nb_warp, 512>>>(Whh + (m + 1) * HID * HID);
        else
            k_combine_gemm<NCLS><<<nb_warp, 512>>>(Wl);
    }

    // final GCN aggregation (32 -> 40 classes)
    k_agg40<<<nb_warp, 512>>>(bl, out);
}